// round 6
// baseline (speedup 1.0000x reference)
#include <cuda_runtime.h>

#define FULL_MASK 0xFFFFFFFFu
static constexpr int HID = 32;
static constexpr int TT = 1024;
static constexpr int WARPS_PER_CTA = 4;

// ---- packed f32x2 helpers (sm_103a; ptxas never auto-fuses these) ----
__device__ __forceinline__ unsigned long long pack2(float lo, float hi) {
    unsigned long long r;
    asm("mov.b64 %0, {%1, %2};" : "=l"(r) : "f"(lo), "f"(hi));
    return r;
}
__device__ __forceinline__ void unpack2(unsigned long long v, float& lo, float& hi) {
    asm("mov.b64 {%0, %1}, %2;" : "=f"(lo), "=f"(hi) : "l"(v));
}
__device__ __forceinline__ unsigned long long fma2(unsigned long long a,
                                                   unsigned long long b,
                                                   unsigned long long c) {
    unsigned long long d;
    asm("fma.rn.f32x2 %0, %1, %2, %3;" : "=l"(d) : "l"(a), "l"(b), "l"(c));
    return d;
}
__device__ __forceinline__ float ex2f(float x) {
    float r; asm("ex2.approx.f32 %0, %1;" : "=f"(r) : "f"(x)); return r;
}
__device__ __forceinline__ float rcpf(float x) {
    float r; asm("rcp.approx.f32 %0, %1;" : "=f"(r) : "f"(x)); return r;
}
// sigmoid(x) = 1 / (1 + 2^(-x*log2(e)))  — ex2/rcp approx are ~2^-22 rel err
__device__ __forceinline__ float fast_sigmoid(float x) {
    return rcpf(1.0f + ex2f(-1.4426950408889634f * x));
}
// tanh(x) = 2*sigmoid(2x) - 1
__device__ __forceinline__ float fast_tanh(float x) {
    float r = rcpf(1.0f + ex2f(-2.8853900817779268f * x));
    return fmaf(2.0f, r, -1.0f);
}

// TWO cells per warp, k-packed weights shared between them.
// Weights: Wg[gate][k2] = (w[lane][2k2], w[lane][2k2+1]) as f32x2 — 128 regs.
// h stored SCALAR in smem; LDS.64 broadcast of (h_{2k}, h_{2k+1}) is directly
// the fma2 multiplicand. 8 independent 16-deep chains per step (4 gates x 2
// cells): 256 fma-pipe cycles per warp-step vs ~64-cycle chain depth — the
// warp self-saturates the fma pipe; 3 warps/SMSP oversubscribe it.
__global__ void __launch_bounds__(WARPS_PER_CTA * 32, 3)
lstm_kernel(const float* __restrict__ x,
            const float* __restrict__ W_ih,
            const float* __restrict__ W_hh,
            const float* __restrict__ b_ih,
            const float* __restrict__ b_hh,
            const float* __restrict__ fc_W,
            const float* __restrict__ fc_b,
            float* __restrict__ out, int B)
{
    __shared__ __align__(8) float hbuf[WARPS_PER_CTA][2][2][HID]; // [warp][cell][pp][k]
    const int warp = threadIdx.x >> 5;
    const int lane = threadIdx.x & 31;
    const int b0 = (blockIdx.x * WARPS_PER_CTA + warp) * 2;
    if (b0 >= B) return;   // warp-uniform

    // Gate order (PyTorch): rows [0:32)=i, [32:64)=f, [64:96)=g, [96:128)=o
    unsigned long long Wg[4][HID / 2];
    #pragma unroll
    for (int g = 0; g < 4; ++g) {
        const float* wrow = W_hh + (g * HID + lane) * HID;
        #pragma unroll
        for (int k2 = 0; k2 < HID / 2; ++k2)
            Wg[g][k2] = pack2(wrow[2 * k2], wrow[2 * k2 + 1]);
    }
    const float wih_i = W_ih[0 * HID + lane];
    const float wih_f = W_ih[1 * HID + lane];
    const float wih_g = W_ih[2 * HID + lane];
    const float wih_o = W_ih[3 * HID + lane];
    const float bias_i = b_ih[0 * HID + lane] + b_hh[0 * HID + lane];
    const float bias_f = b_ih[1 * HID + lane] + b_hh[1 * HID + lane];
    const float bias_g = b_ih[2 * HID + lane] + b_hh[2 * HID + lane];
    const float bias_o = b_ih[3 * HID + lane] + b_hh[3 * HID + lane];

    float hA = 0.0f, cA = 0.0f, hB = 0.0f, cB = 0.0f;
    const float* xrowA = x + (size_t)b0 * TT;        // x is [B, T, 1]
    const float* xrowB = xrowA + TT;                 // b0+1 (B even)

    float* bufA0 = hbuf[warp][0][0];
    float* bufB0 = hbuf[warp][1][0];

    for (int t0 = 0; t0 < TT; t0 += 32) {
        const float xbufA = xrowA[t0 + lane];
        const float xbufB = xrowB[t0 + lane];
        #pragma unroll 2
        for (int s = 0; s < 32; ++s) {
            const float xvA = __shfl_sync(FULL_MASK, xbufA, s);
            const float xvB = __shfl_sync(FULL_MASK, xbufB, s);

            float* bufA = bufA0 + (s & 1) * HID;
            float* bufB = bufB0 + (s & 1) * HID;
            bufA[lane] = hA;
            bufB[lane] = hB;
            __syncwarp();

            // gate base folded into accumulator init: acc = (x*wih + bias, 0)
            unsigned long long aiA = pack2(fmaf(xvA, wih_i, bias_i), 0.0f);
            unsigned long long afA = pack2(fmaf(xvA, wih_f, bias_f), 0.0f);
            unsigned long long agA = pack2(fmaf(xvA, wih_g, bias_g), 0.0f);
            unsigned long long aoA = pack2(fmaf(xvA, wih_o, bias_o), 0.0f);
            unsigned long long aiB = pack2(fmaf(xvB, wih_i, bias_i), 0.0f);
            unsigned long long afB = pack2(fmaf(xvB, wih_f, bias_f), 0.0f);
            unsigned long long agB = pack2(fmaf(xvB, wih_g, bias_g), 0.0f);
            unsigned long long aoB = pack2(fmaf(xvB, wih_o, bias_o), 0.0f);

            const unsigned long long* hpA =
                reinterpret_cast<const unsigned long long*>(bufA);
            const unsigned long long* hpB =
                reinterpret_cast<const unsigned long long*>(bufB);
            #pragma unroll
            for (int k2 = 0; k2 < HID / 2; ++k2) {
                const unsigned long long hkA = hpA[k2];  // LDS.64 broadcast
                const unsigned long long hkB = hpB[k2];
                aiA = fma2(Wg[0][k2], hkA, aiA);
                afA = fma2(Wg[1][k2], hkA, afA);
                agA = fma2(Wg[2][k2], hkA, agA);
                aoA = fma2(Wg[3][k2], hkA, aoA);
                aiB = fma2(Wg[0][k2], hkB, aiB);
                afB = fma2(Wg[1][k2], hkB, afB);
                agB = fma2(Wg[2][k2], hkB, agB);
                aoB = fma2(Wg[3][k2], hkB, aoB);
            }

            float lo, hi;
            unpack2(aiA, lo, hi);  const float giA = lo + hi;
            unpack2(afA, lo, hi);  const float gfA = lo + hi;
            unpack2(agA, lo, hi);  const float ggA = lo + hi;
            unpack2(aoA, lo, hi);  const float goA = lo + hi;
            unpack2(aiB, lo, hi);  const float giB = lo + hi;
            unpack2(afB, lo, hi);  const float gfB = lo + hi;
            unpack2(agB, lo, hi);  const float ggB = lo + hi;
            unpack2(aoB, lo, hi);  const float goB = lo + hi;

            const float igA = fast_sigmoid(giA);
            const float fgA = fast_sigmoid(gfA);
            const float cgA = fast_tanh(ggA);
            const float ogA = fast_sigmoid(goA);
            const float igB = fast_sigmoid(giB);
            const float fgB = fast_sigmoid(gfB);
            const float cgB = fast_tanh(ggB);
            const float ogB = fast_sigmoid(goB);

            cA = fmaf(fgA, cA, igA * cgA);
            cB = fmaf(fgB, cB, igB * cgB);
            hA = ogA * fast_tanh(cA);
            hB = ogB * fast_tanh(cB);
        }
    }

    // out[b] = h . fc_W + fc_b  (warp reduce, both cells)
    const float w = fc_W[lane];
    float vA = hA * w;
    float vB = hB * w;
    #pragma unroll
    for (int off = 16; off; off >>= 1) {
        vA += __shfl_xor_sync(FULL_MASK, vA, off);
        vB += __shfl_xor_sync(FULL_MASK, vB, off);
    }
    if (lane == 0) {
        const float fcb = fc_b[0];
        out[b0] = vA + fcb;
        out[b0 + 1] = vB + fcb;
    }
}

extern "C" void kernel_launch(void* const* d_in, const int* in_sizes, int n_in,
                              void* d_out, int out_size) {
    const float* x    = (const float*)d_in[0];
    const float* W_ih = (const float*)d_in[1];
    const float* W_hh = (const float*)d_in[2];
    const float* b_ih = (const float*)d_in[3];
    const float* b_hh = (const float*)d_in[4];
    const float* fc_W = (const float*)d_in[5];
    const float* fc_b = (const float*)d_in[6];
    float* out = (float*)d_out;

    const int B = in_sizes[0] / TT;           // x is B*T*1 elements
    const int cells_per_cta = WARPS_PER_CTA * 2;
    const int ctas = (B + cells_per_cta - 1) / cells_per_cta;
    lstm_kernel<<<ctas, WARPS_PER_CTA * 32>>>(x, W_ih, W_hh, b_ih, b_hh,
                                              fc_W, fc_b, out, B);
}

// round 7
// speedup vs baseline: 1.0345x; 1.0345x over previous
#include <cuda_runtime.h>

#define FULL_MASK 0xFFFFFFFFu
static constexpr int HID = 32;
static constexpr int TT = 1024;
static constexpr int WARPS_PER_CTA = 4;

// ---- packed f32x2 helpers (sm_103a; ptxas never auto-fuses these) ----
__device__ __forceinline__ unsigned long long pack2(float lo, float hi) {
    unsigned long long r;
    asm("mov.b64 %0, {%1, %2};" : "=l"(r) : "f"(lo), "f"(hi));
    return r;
}
__device__ __forceinline__ void unpack2(unsigned long long v, float& lo, float& hi) {
    asm("mov.b64 {%0, %1}, %2;" : "=f"(lo), "=f"(hi) : "l"(v));
}
__device__ __forceinline__ unsigned long long fma2(unsigned long long a,
                                                   unsigned long long b,
                                                   unsigned long long c) {
    unsigned long long d;
    asm("fma.rn.f32x2 %0, %1, %2, %3;" : "=l"(d) : "l"(a), "l"(b), "l"(c));
    return d;
}
__device__ __forceinline__ float ex2f(float x) {
    float r; asm("ex2.approx.f32 %0, %1;" : "=f"(r) : "f"(x)); return r;
}
__device__ __forceinline__ float rcpf(float x) {
    float r; asm("rcp.approx.f32 %0, %1;" : "=f"(r) : "f"(x)); return r;
}
// sigmoid(x) = 1 / (1 + 2^(-x*log2(e)))  — ex2/rcp approx are ~2^-22 rel err
__device__ __forceinline__ float fast_sigmoid(float x) {
    return rcpf(1.0f + ex2f(-1.4426950408889634f * x));
}
// tanh(x) = 2*sigmoid(2x) - 1
__device__ __forceinline__ float fast_tanh(float x) {
    float r = rcpf(1.0f + ex2f(-2.8853900817779268f * x));
    return fmaf(2.0f, r, -1.0f);
}

// TWO cells per warp, k-packed weights shared between them (128 regs).
// KEY FIX vs R6: __launch_bounds__(128, 2) -> 256-reg cap. The 2-cell kernel
// needs ~190 live regs; at minBlocks=3 (170-reg cap) ptxas spilled the hot
// loop. 2 CTAs/SM = 2 warps/SMSP, each carrying 256 fma-pipe-cycles of
// independent work per step -> fma pipe becomes the binding resource.
__global__ void __launch_bounds__(WARPS_PER_CTA * 32, 2)
lstm_kernel(const float* __restrict__ x,
            const float* __restrict__ W_ih,
            const float* __restrict__ W_hh,
            const float* __restrict__ b_ih,
            const float* __restrict__ b_hh,
            const float* __restrict__ fc_W,
            const float* __restrict__ fc_b,
            float* __restrict__ out, int B)
{
    __shared__ __align__(8) float hbuf[WARPS_PER_CTA][2][2][HID]; // [warp][cell][pp][k]
    const int warp = threadIdx.x >> 5;
    const int lane = threadIdx.x & 31;
    const int b0 = (blockIdx.x * WARPS_PER_CTA + warp) * 2;
    if (b0 >= B) return;   // warp-uniform

    // Gate order (PyTorch): rows [0:32)=i, [32:64)=f, [64:96)=g, [96:128)=o
    unsigned long long Wg[4][HID / 2];
    #pragma unroll
    for (int g = 0; g < 4; ++g) {
        const float* wrow = W_hh + (g * HID + lane) * HID;
        #pragma unroll
        for (int k2 = 0; k2 < HID / 2; ++k2)
            Wg[g][k2] = pack2(wrow[2 * k2], wrow[2 * k2 + 1]);
    }
    const float wih_i = W_ih[0 * HID + lane];
    const float wih_f = W_ih[1 * HID + lane];
    const float wih_g = W_ih[2 * HID + lane];
    const float wih_o = W_ih[3 * HID + lane];
    const float bias_i = b_ih[0 * HID + lane] + b_hh[0 * HID + lane];
    const float bias_f = b_ih[1 * HID + lane] + b_hh[1 * HID + lane];
    const float bias_g = b_ih[2 * HID + lane] + b_hh[2 * HID + lane];
    const float bias_o = b_ih[3 * HID + lane] + b_hh[3 * HID + lane];

    float hA = 0.0f, cA = 0.0f, hB = 0.0f, cB = 0.0f;
    const float* xrowA = x + (size_t)b0 * TT;        // x is [B, T, 1]
    const float* xrowB = xrowA + TT;                 // b0+1 (B even)

    float* bufA0 = hbuf[warp][0][0];
    float* bufB0 = hbuf[warp][1][0];

    for (int t0 = 0; t0 < TT; t0 += 32) {
        const float xbufA = xrowA[t0 + lane];
        const float xbufB = xrowB[t0 + lane];
        #pragma unroll 1   // 2-cell body ~4KB SASS; unroll would blow L0 I$
        for (int s = 0; s < 32; ++s) {
            const float xvA = __shfl_sync(FULL_MASK, xbufA, s);
            const float xvB = __shfl_sync(FULL_MASK, xbufB, s);

            float* bufA = bufA0 + (s & 1) * HID;
            float* bufB = bufB0 + (s & 1) * HID;
            bufA[lane] = hA;
            bufB[lane] = hB;
            __syncwarp();

            // gate base folded into accumulator init: acc = (x*wih + bias, 0)
            unsigned long long aiA = pack2(fmaf(xvA, wih_i, bias_i), 0.0f);
            unsigned long long afA = pack2(fmaf(xvA, wih_f, bias_f), 0.0f);
            unsigned long long agA = pack2(fmaf(xvA, wih_g, bias_g), 0.0f);
            unsigned long long aoA = pack2(fmaf(xvA, wih_o, bias_o), 0.0f);
            unsigned long long aiB = pack2(fmaf(xvB, wih_i, bias_i), 0.0f);
            unsigned long long afB = pack2(fmaf(xvB, wih_f, bias_f), 0.0f);
            unsigned long long agB = pack2(fmaf(xvB, wih_g, bias_g), 0.0f);
            unsigned long long aoB = pack2(fmaf(xvB, wih_o, bias_o), 0.0f);

            const unsigned long long* hpA =
                reinterpret_cast<const unsigned long long*>(bufA);
            const unsigned long long* hpB =
                reinterpret_cast<const unsigned long long*>(bufB);
            #pragma unroll
            for (int k2 = 0; k2 < HID / 2; ++k2) {
                const unsigned long long hkA = hpA[k2];  // LDS.64 broadcast
                const unsigned long long hkB = hpB[k2];
                aiA = fma2(Wg[0][k2], hkA, aiA);
                afA = fma2(Wg[1][k2], hkA, afA);
                agA = fma2(Wg[2][k2], hkA, agA);
                aoA = fma2(Wg[3][k2], hkA, aoA);
                aiB = fma2(Wg[0][k2], hkB, aiB);
                afB = fma2(Wg[1][k2], hkB, afB);
                agB = fma2(Wg[2][k2], hkB, agB);
                aoB = fma2(Wg[3][k2], hkB, aoB);
            }

            float lo, hi;
            unpack2(aiA, lo, hi);  const float giA = lo + hi;
            unpack2(afA, lo, hi);  const float gfA = lo + hi;
            unpack2(agA, lo, hi);  const float ggA = lo + hi;
            unpack2(aoA, lo, hi);  const float goA = lo + hi;
            unpack2(aiB, lo, hi);  const float giB = lo + hi;
            unpack2(afB, lo, hi);  const float gfB = lo + hi;
            unpack2(agB, lo, hi);  const float ggB = lo + hi;
            unpack2(aoB, lo, hi);  const float goB = lo + hi;

            const float igA = fast_sigmoid(giA);
            const float fgA = fast_sigmoid(gfA);
            const float cgA = fast_tanh(ggA);
            const float ogA = fast_sigmoid(goA);
            const float igB = fast_sigmoid(giB);
            const float fgB = fast_sigmoid(gfB);
            const float cgB = fast_tanh(ggB);
            const float ogB = fast_sigmoid(goB);

            cA = fmaf(fgA, cA, igA * cgA);
            cB = fmaf(fgB, cB, igB * cgB);
            hA = ogA * fast_tanh(cA);
            hB = ogB * fast_tanh(cB);
        }
    }

    // out[b] = h . fc_W + fc_b  (warp reduce, both cells)
    const float w = fc_W[lane];
    float vA = hA * w;
    float vB = hB * w;
    #pragma unroll
    for (int off = 16; off; off >>= 1) {
        vA += __shfl_xor_sync(FULL_MASK, vA, off);
        vB += __shfl_xor_sync(FULL_MASK, vB, off);
    }
    if (lane == 0) {
        const float fcb = fc_b[0];
        out[b0] = vA + fcb;
        out[b0 + 1] = vB + fcb;
    }
}

extern "C" void kernel_launch(void* const* d_in, const int* in_sizes, int n_in,
                              void* d_out, int out_size) {
    const float* x    = (const float*)d_in[0];
    const float* W_ih = (const float*)d_in[1];
    const float* W_hh = (const float*)d_in[2];
    const float* b_ih = (const float*)d_in[3];
    const float* b_hh = (const float*)d_in[4];
    const float* fc_W = (const float*)d_in[5];
    const float* fc_b = (const float*)d_in[6];
    float* out = (float*)d_out;

    const int B = in_sizes[0] / TT;           // x is B*T*1 elements
    const int cells_per_cta = WARPS_PER_CTA * 2;
    const int ctas = (B + cells_per_cta - 1) / cells_per_cta;
    lstm_kernel<<<ctas, WARPS_PER_CTA * 32>>>(x, W_ih, W_hh, b_ih, b_hh,
                                              fc_W, fc_b, out, B);
}

// round 8
// speedup vs baseline: 1.1325x; 1.0947x over previous
#include <cuda_runtime.h>

#define FULL_MASK 0xFFFFFFFFu
static constexpr int HID = 32;
static constexpr int TT = 1024;
static constexpr int WARPS_PER_CTA = 4;

// log2(e) folding constants (prescaled into weights at load time)
#define NEG_L2E  (-1.4426950408889634f)
#define NEG_2L2E (-2.8853900817779268f)

// ---- packed f32x2 helpers (sm_103a; ptxas never auto-fuses these) ----
__device__ __forceinline__ unsigned long long pack2(float lo, float hi) {
    unsigned long long r;
    asm("mov.b64 %0, {%1, %2};" : "=l"(r) : "f"(lo), "f"(hi));
    return r;
}
__device__ __forceinline__ void unpack2(unsigned long long v, float& lo, float& hi) {
    asm("mov.b64 {%0, %1}, %2;" : "=f"(lo), "=f"(hi) : "l"(v));
}
__device__ __forceinline__ unsigned long long fma2(unsigned long long a,
                                                   unsigned long long b,
                                                   unsigned long long c) {
    unsigned long long d;
    asm("fma.rn.f32x2 %0, %1, %2, %3;" : "=l"(d) : "l"(a), "l"(b), "l"(c));
    return d;
}
__device__ __forceinline__ float ex2f(float x) {
    float r; asm("ex2.approx.f32 %0, %1;" : "=f"(r) : "f"(x)); return r;
}
__device__ __forceinline__ float rcpf(float x) {
    float r; asm("rcp.approx.f32 %0, %1;" : "=f"(r) : "f"(x)); return r;
}
// PRESCALED forms: input already multiplied by -log2e (sigmoid) or -2log2e (tanh)
__device__ __forceinline__ float sigmoid_ps(float s) {   // s = -log2e * x
    return rcpf(1.0f + ex2f(s));
}
__device__ __forceinline__ float tanh_ps(float s) {      // s = -2*log2e * x
    return fmaf(2.0f, rcpf(1.0f + ex2f(s)), -1.0f);
}
// natural-domain tanh (for tanh(c))
__device__ __forceinline__ float fast_tanh(float x) {
    return fmaf(2.0f, rcpf(1.0f + ex2f(NEG_2L2E * x)), -1.0f);
}

// One warp per cell, lane j owns hidden unit j. k-packed weights (128 regs),
// PRESCALED by the activation log2e constants so every sigmoid/tanh(gate)
// starts directly at MUFU.EX2. h stored scalar in smem; LDS.128 broadcast
// yields TWO packed (h_{2k},h_{2k+1}) multiplicands per load (8 loads/step).
// Gate base (x*W_ih + bias, prescaled) folded into accumulator init.
__global__ void __launch_bounds__(WARPS_PER_CTA * 32, 3)
lstm_kernel(const float* __restrict__ x,
            const float* __restrict__ W_ih,
            const float* __restrict__ W_hh,
            const float* __restrict__ b_ih,
            const float* __restrict__ b_hh,
            const float* __restrict__ fc_W,
            const float* __restrict__ fc_b,
            float* __restrict__ out, int B)
{
    __shared__ __align__(16) float hbuf[WARPS_PER_CTA][2][HID];
    const int warp = threadIdx.x >> 5;
    const int lane = threadIdx.x & 31;
    const int b = blockIdx.x * WARPS_PER_CTA + warp;
    if (b >= B) return;   // warp-uniform

    // Gate order (PyTorch): rows [0:32)=i, [32:64)=f, [64:96)=g, [96:128)=o
    // Prescale: i,f,o by -log2e (sigmoid), g by -2log2e (tanh).
    const float gscale[4] = { NEG_L2E, NEG_L2E, NEG_2L2E, NEG_L2E };
    unsigned long long Wg[4][HID / 2];
    #pragma unroll
    for (int g = 0; g < 4; ++g) {
        const float* wrow = W_hh + (g * HID + lane) * HID;
        const float sc = gscale[g];
        #pragma unroll
        for (int k2 = 0; k2 < HID / 2; ++k2)
            Wg[g][k2] = pack2(sc * wrow[2 * k2], sc * wrow[2 * k2 + 1]);
    }
    const float wih_i = NEG_L2E  * W_ih[0 * HID + lane];
    const float wih_f = NEG_L2E  * W_ih[1 * HID + lane];
    const float wih_g = NEG_2L2E * W_ih[2 * HID + lane];
    const float wih_o = NEG_L2E  * W_ih[3 * HID + lane];
    const float bias_i = NEG_L2E  * (b_ih[0 * HID + lane] + b_hh[0 * HID + lane]);
    const float bias_f = NEG_L2E  * (b_ih[1 * HID + lane] + b_hh[1 * HID + lane]);
    const float bias_g = NEG_2L2E * (b_ih[2 * HID + lane] + b_hh[2 * HID + lane]);
    const float bias_o = NEG_L2E  * (b_ih[3 * HID + lane] + b_hh[3 * HID + lane]);

    float h = 0.0f, c = 0.0f;
    const float* xrow = x + (size_t)b * TT;   // x is [B, T, 1]

    for (int t0 = 0; t0 < TT; t0 += 32) {
        // one coalesced 128B read per warp per 32 steps
        const float xbuf = xrow[t0 + lane];
        #pragma unroll 1
        for (int s = 0; s < 32; ++s) {
            const float xv = __shfl_sync(FULL_MASK, xbuf, s);

            float* buf = hbuf[warp][s & 1];
            buf[lane] = h;
            __syncwarp();

            // acc init = (prescaled gate base, 0)
            unsigned long long ai = pack2(fmaf(xv, wih_i, bias_i), 0.0f);
            unsigned long long af = pack2(fmaf(xv, wih_f, bias_f), 0.0f);
            unsigned long long ag = pack2(fmaf(xv, wih_g, bias_g), 0.0f);
            unsigned long long ao = pack2(fmaf(xv, wih_o, bias_o), 0.0f);

            const ulonglong2* hp = reinterpret_cast<const ulonglong2*>(buf);
            #pragma unroll
            for (int k4 = 0; k4 < HID / 4; ++k4) {
                const ulonglong2 hk = hp[k4];   // LDS.128 broadcast: 2 h-pairs
                ai = fma2(Wg[0][2 * k4], hk.x, ai);
                af = fma2(Wg[1][2 * k4], hk.x, af);
                ag = fma2(Wg[2][2 * k4], hk.x, ag);
                ao = fma2(Wg[3][2 * k4], hk.x, ao);
                ai = fma2(Wg[0][2 * k4 + 1], hk.y, ai);
                af = fma2(Wg[1][2 * k4 + 1], hk.y, af);
                ag = fma2(Wg[2][2 * k4 + 1], hk.y, ag);
                ao = fma2(Wg[3][2 * k4 + 1], hk.y, ao);
            }

            float lo, hi;
            unpack2(ai, lo, hi);  const float ig = sigmoid_ps(lo + hi);
            unpack2(af, lo, hi);  const float fg = sigmoid_ps(lo + hi);
            unpack2(ag, lo, hi);  const float gg = tanh_ps(lo + hi);
            unpack2(ao, lo, hi);  const float og = sigmoid_ps(lo + hi);

            c = fmaf(fg, c, ig * gg);
            h = og * fast_tanh(c);
        }
    }

    // out[b] = h . fc_W + fc_b  (warp reduce)
    float v = h * fc_W[lane];
    #pragma unroll
    for (int off = 16; off; off >>= 1)
        v += __shfl_xor_sync(FULL_MASK, v, off);
    if (lane == 0) out[b] = v + fc_b[0];
}

extern "C" void kernel_launch(void* const* d_in, const int* in_sizes, int n_in,
                              void* d_out, int out_size) {
    const float* x    = (const float*)d_in[0];
    const float* W_ih = (const float*)d_in[1];
    const float* W_hh = (const float*)d_in[2];
    const float* b_ih = (const float*)d_in[3];
    const float* b_hh = (const float*)d_in[4];
    const float* fc_W = (const float*)d_in[5];
    const float* fc_b = (const float*)d_in[6];
    float* out = (float*)d_out;

    const int B = in_sizes[0] / TT;           // x is B*T*1 elements
    const int ctas = (B + WARPS_PER_CTA - 1) / WARPS_PER_CTA;
    lstm_kernel<<<ctas, WARPS_PER_CTA * 32>>>(x, W_ih, W_hh, b_ih, b_hh,
                                              fc_W, fc_b, out, B);
}

// round 9
// speedup vs baseline: 1.4390x; 1.2707x over previous
#include <cuda_runtime.h>

#define FULL_MASK 0xFFFFFFFFu
static constexpr int HID = 32;
static constexpr int TT = 1024;
static constexpr int WARPS_PER_CTA = 4;

// ---- packed f32x2 helpers (sm_103a; ptxas never auto-fuses these) ----
__device__ __forceinline__ unsigned long long pack2(float lo, float hi) {
    unsigned long long r;
    asm("mov.b64 %0, {%1, %2};" : "=l"(r) : "f"(lo), "f"(hi));
    return r;
}
__device__ __forceinline__ void unpack2(unsigned long long v, float& lo, float& hi) {
    asm("mov.b64 {%0, %1}, %2;" : "=f"(lo), "=f"(hi) : "l"(v));
}
__device__ __forceinline__ unsigned long long fma2(unsigned long long a,
                                                   unsigned long long b,
                                                   unsigned long long c) {
    unsigned long long d;
    asm("fma.rn.f32x2 %0, %1, %2, %3;" : "=l"(d) : "l"(a), "l"(b), "l"(c));
    return d;
}
// single-MUFU tanh (MUFU.TANH, sm_75+; rel err ~2^-11)
__device__ __forceinline__ float tanh_approx(float x) {
    float r; asm("tanh.approx.f32 %0, %1;" : "=f"(r) : "f"(x)); return r;
}

// One warp per cell, lane j owns hidden unit j. k-packed weights (128 regs).
// ACTIVATIONS: one MUFU.TANH each.
//   sigmoid(x) = 0.5 + 0.5*tanh(x/2)  -- the /2 is PRESCALED into the i,f,o
//   weight rows and biases at load time, so mainloop cost is 1 MUFU + 1 FMA.
//   g-gate and tanh(c) use tanh.approx directly.
// MUFU demand/step: 10 ops -> 5 ops; activation cascade ~80 -> ~25 cycles.
__global__ void __launch_bounds__(WARPS_PER_CTA * 32, 3)
lstm_kernel(const float* __restrict__ x,
            const float* __restrict__ W_ih,
            const float* __restrict__ W_hh,
            const float* __restrict__ b_ih,
            const float* __restrict__ b_hh,
            const float* __restrict__ fc_W,
            const float* __restrict__ fc_b,
            float* __restrict__ out, int B)
{
    __shared__ __align__(16) float hbuf[WARPS_PER_CTA][2][HID];
    const int warp = threadIdx.x >> 5;
    const int lane = threadIdx.x & 31;
    const int b = blockIdx.x * WARPS_PER_CTA + warp;
    if (b >= B) return;   // warp-uniform

    // Gate order (PyTorch): rows [0:32)=i, [32:64)=f, [64:96)=g, [96:128)=o
    // Prescale i,f,o rows by 0.5 (sigmoid-via-tanh); g row unscaled.
    const float gscale[4] = { 0.5f, 0.5f, 1.0f, 0.5f };
    unsigned long long Wg[4][HID / 2];
    #pragma unroll
    for (int g = 0; g < 4; ++g) {
        const float* wrow = W_hh + (g * HID + lane) * HID;
        const float sc = gscale[g];
        #pragma unroll
        for (int k2 = 0; k2 < HID / 2; ++k2)
            Wg[g][k2] = pack2(sc * wrow[2 * k2], sc * wrow[2 * k2 + 1]);
    }
    const float wih_i = 0.5f * W_ih[0 * HID + lane];
    const float wih_f = 0.5f * W_ih[1 * HID + lane];
    const float wih_g =        W_ih[2 * HID + lane];
    const float wih_o = 0.5f * W_ih[3 * HID + lane];
    const float bias_i = 0.5f * (b_ih[0 * HID + lane] + b_hh[0 * HID + lane]);
    const float bias_f = 0.5f * (b_ih[1 * HID + lane] + b_hh[1 * HID + lane]);
    const float bias_g =        (b_ih[2 * HID + lane] + b_hh[2 * HID + lane]);
    const float bias_o = 0.5f * (b_ih[3 * HID + lane] + b_hh[3 * HID + lane]);

    float h = 0.0f, c = 0.0f;
    const float* xrow = x + (size_t)b * TT;   // x is [B, T, 1]

    for (int t0 = 0; t0 < TT; t0 += 32) {
        // one coalesced 128B read per warp per 32 steps
        const float xbuf = xrow[t0 + lane];
        #pragma unroll 1
        for (int s = 0; s < 32; ++s) {
            const float xv = __shfl_sync(FULL_MASK, xbuf, s);

            float* buf = hbuf[warp][s & 1];
            buf[lane] = h;
            __syncwarp();

            // acc init = (prescaled gate base, 0)
            unsigned long long ai = pack2(fmaf(xv, wih_i, bias_i), 0.0f);
            unsigned long long af = pack2(fmaf(xv, wih_f, bias_f), 0.0f);
            unsigned long long ag = pack2(fmaf(xv, wih_g, bias_g), 0.0f);
            unsigned long long ao = pack2(fmaf(xv, wih_o, bias_o), 0.0f);

            const ulonglong2* hp = reinterpret_cast<const ulonglong2*>(buf);
            #pragma unroll
            for (int k4 = 0; k4 < HID / 4; ++k4) {
                const ulonglong2 hk = hp[k4];   // LDS.128 broadcast: 2 h-pairs
                ai = fma2(Wg[0][2 * k4], hk.x, ai);
                af = fma2(Wg[1][2 * k4], hk.x, af);
                ag = fma2(Wg[2][2 * k4], hk.x, ag);
                ao = fma2(Wg[3][2 * k4], hk.x, ao);
                ai = fma2(Wg[0][2 * k4 + 1], hk.y, ai);
                af = fma2(Wg[1][2 * k4 + 1], hk.y, af);
                ag = fma2(Wg[2][2 * k4 + 1], hk.y, ag);
                ao = fma2(Wg[3][2 * k4 + 1], hk.y, ao);
            }

            float lo, hi;
            unpack2(ai, lo, hi);  const float ti = tanh_approx(lo + hi);
            unpack2(af, lo, hi);  const float tf = tanh_approx(lo + hi);
            unpack2(ag, lo, hi);  const float gg = tanh_approx(lo + hi);
            unpack2(ao, lo, hi);  const float to = tanh_approx(lo + hi);

            const float ig = fmaf(0.5f, ti, 0.5f);
            const float fg = fmaf(0.5f, tf, 0.5f);
            const float og = fmaf(0.5f, to, 0.5f);

            c = fmaf(fg, c, ig * gg);
            h = og * tanh_approx(c);
        }
    }

    // out[b] = h . fc_W + fc_b  (warp reduce)
    float v = h * fc_W[lane];
    #pragma unroll
    for (int off = 16; off; off >>= 1)
        v += __shfl_xor_sync(FULL_MASK, v, off);
    if (lane == 0) out[b] = v + fc_b[0];
}

extern "C" void kernel_launch(void* const* d_in, const int* in_sizes, int n_in,
                              void* d_out, int out_size) {
    const float* x    = (const float*)d_in[0];
    const float* W_ih = (const float*)d_in[1];
    const float* W_hh = (const float*)d_in[2];
    const float* b_ih = (const float*)d_in[3];
    const float* b_hh = (const float*)d_in[4];
    const float* fc_W = (const float*)d_in[5];
    const float* fc_b = (const float*)d_in[6];
    float* out = (float*)d_out;

    const int B = in_sizes[0] / TT;           // x is B*T*1 elements
    const int ctas = (B + WARPS_PER_CTA - 1) / WARPS_PER_CTA;
    lstm_kernel<<<ctas, WARPS_PER_CTA * 32>>>(x, W_ih, W_hh, b_ih, b_hh,
                                              fc_W, fc_b, out, B);
}